// round 11
// baseline (speedup 1.0000x reference)
#include <cuda_runtime.h>

#define DD   512
#define KK   16
#define TPB  256           // 8 warps = 4 pairs; pair owns 64 rows; warp owns 8 k
#define RPB  256           // rows per block
#define CH   16            // dims per chunk = 64B per row
#define NCH  (DD/CH)       // 32 chunks

// ---- dynamic smem layout (bytes) ----
#define SM_CB     0                      // codebook: 32768
#define SM_ZSTG   32768                  // staging: 2 stages * 8 warps * 4096 = 65536
#define SM_SDIST  98304                  // 2 * 256 * 4 = 2048
#define SM_SIDX   100352                 // 2 * 256 * 4 = 2048
#define SM_C2S    102400                 // 16 * 4
#define SM_TICKET 102464                 // 4
#define SM_TOTAL  102528

// ---- device scratch (no allocations allowed) ----
__device__ float g_bsum[4096];
__device__ unsigned int g_done = 0;

// ---- packed f32x2 helpers (Blackwell FFMA2) ----
__device__ __forceinline__ void upk2(unsigned long long v, float& lo, float& hi) {
    asm("mov.b64 {%0,%1}, %2;" : "=f"(lo), "=f"(hi) : "l"(v));
}
__device__ __forceinline__ unsigned long long ffma2(unsigned long long a,
                                                    unsigned long long b,
                                                    unsigned long long c) {
    unsigned long long d;
    asm("fma.rn.f32x2 %0, %1, %2, %3;" : "=l"(d) : "l"(a), "l"(b), "l"(c));
    return d;
}
__device__ __forceinline__ void cpasync16(unsigned dst, const void* src) {
    asm volatile("cp.async.cg.shared.global [%0], [%1], 16;" :: "r"(dst), "l"(src) : "memory");
}
#define CP_COMMIT() asm volatile("cp.async.commit_group;" ::: "memory")
#define CP_WAIT(n)  asm volatile("cp.async.wait_group %0;" :: "n"(n) : "memory")

__global__ void __launch_bounds__(TPB, 2) vq_fused(
    const float* __restrict__ z, const float* __restrict__ cb,
    float* __restrict__ zq, float* __restrict__ idxp, float* __restrict__ lossp,
    int nrows, int nblocks, float scale)
{
    extern __shared__ char smem[];
    float*        sc     = (float*)(smem + SM_CB);
    float*        sdist  = (float*)(smem + SM_SDIST);   // [2][256]
    int*          sidx   = (int*)(smem + SM_SIDX);      // [2][256]
    float*        c2s    = (float*)(smem + SM_C2S);
    unsigned int* ticket = (unsigned int*)(smem + SM_TICKET);

    const int t = threadIdx.x;
    const int w = t >> 5, lane = t & 31;
    const int p     = w >> 1;            // pair id: rows p*64..p*64+63
    const int h     = w & 1;             // k-half
    const int khalf = h * 8;
    const int rowbase = blockIdx.x * RPB;
    const int lastrow = nrows - 1;

    const unsigned smem_sa = (unsigned)__cvta_generic_to_shared(smem);
    // private staging for (stage s, warp w): SM_ZSTG + (s*8+w)*4096
    // inside: piece*1024 + row*16  (piece = 4 dims = 16B, row in [0,64))
    const unsigned stg_w = smem_sa + SM_ZSTG + (unsigned)(w * 4096);

    // cp.async roles: instr i stages row i*8 + (lane>>2), piece = lane&3
    const int srow = lane >> 2;          // 0..7
    const int sp   = lane & 3;           // 0..3

    #define ISSUE(c, s) do {                                                        \
        _Pragma("unroll")                                                           \
        for (int i = 0; i < 8; i++) {                                               \
            int rr = i * 8 + srow;                                                  \
            int gr = rowbase + p * 64 + rr; if (gr > lastrow) gr = lastrow;         \
            const char* src = (const char*)z + (size_t)gr * (DD * 4)                \
                              + (size_t)(c) * (CH * 4) + sp * 16;                   \
            unsigned dst = stg_w + (unsigned)((s) * 32768)                          \
                           + (unsigned)(sp * 1024 + rr * 16);                       \
            cpasync16(dst, src);                                                    \
        }                                                                           \
        CP_COMMIT();                                                                \
    } while (0)

    // ---- prologue: stage chunk 0 ----
    ISSUE(0, 0);

    // ---- stage codebook (coalesced float4) ----
    for (int i = t; i < KK * DD / 4; i += TPB)
        ((float4*)sc)[i] = ((const float4*)cb)[i];
    __syncthreads();

    // ---- codebook squared norms (identical per-k arithmetic as before) ----
    #pragma unroll
    for (int kk = 0; kk < 2; kk++) {
        int k = w * 2 + kk;
        float s = 0.f;
        for (int j = lane; j < DD; j += 32) {
            float v = sc[k * DD + j];
            s = fmaf(v, v, s);
        }
        #pragma unroll
        for (int o = 16; o; o >>= 1) s += __shfl_xor_sync(0xffffffffu, s, o);
        if (lane == 0) c2s[k] = s;
    }
    __syncthreads();                     // c2s + sc visible; no block syncs until epilogue

    // ---- accumulators: 8 k x 2 rows, single chain each (16 ull total) ----
    unsigned long long acc0[8], acc1[8];
    #pragma unroll
    for (int k = 0; k < 8; k++) { acc0[k] = 0ull; acc1[k] = 0ull; }
    unsigned long long z2r0 = 0ull, z2r1 = 0ull;

    const char* stg_rd = (const char*)smem + SM_ZSTG + w * 4096;

    for (int c = 0; c < NCH; c++) {
        if (c + 1 < NCH) {
            ISSUE(c + 1, (c + 1) & 1);   // overlaps chunk c wait + compute
            CP_WAIT(1);                  // chunk c complete, c+1 in flight
        } else {
            CP_WAIT(0);
        }
        __syncwarp();                    // warp-local staging visibility

        const char* rb = stg_rd + (c & 1) * 32768;
        const float* cbb = sc + (khalf * DD + c * CH);

        #pragma unroll
        for (int g = 0; g < 4; g++) {    // 4 pieces x 4 dims, ascending
            ulonglong2 zv0 = *(const ulonglong2*)(rb + g * 1024 + lane * 16);
            ulonglong2 zv1 = *(const ulonglong2*)(rb + g * 1024 + (lane + 32) * 16);
            z2r0 = ffma2(zv0.x, zv0.x, z2r0);  z2r0 = ffma2(zv0.y, zv0.y, z2r0);
            z2r1 = ffma2(zv1.x, zv1.x, z2r1);  z2r1 = ffma2(zv1.y, zv1.y, z2r1);
            #pragma unroll
            for (int k = 0; k < 8; k++) {
                // broadcast LDS.128 (same address across lanes), feeds BOTH rows
                ulonglong2 cv = *(const ulonglong2*)(cbb + k * DD + g * 4);
                acc0[k] = ffma2(zv0.x, cv.x, acc0[k]);
                acc0[k] = ffma2(zv0.y, cv.y, acc0[k]);
                acc1[k] = ffma2(zv1.x, cv.x, acc1[k]);
                acc1[k] = ffma2(zv1.y, cv.y, acc1[k]);
            }
        }
        __syncwarp();                    // all lanes done before next overwrite
    }

    // ---- per-half argmin with reference-matching quantization ----
    const int row0 = p * 64 + lane;      // block-local
    const int row1 = row0 + 32;
    {
        float lo, hi;
        upk2(z2r0, lo, hi);
        float z2s = lo + hi;
        float best = 3.4e38f; int bi = 0;
        #pragma unroll
        for (int k = 0; k < 8; k++) {
            upk2(acc0[k], lo, hi);
            float dot = lo + hi;
            float dist = (z2s - 2.0f * dot) + c2s[khalf + k];
            if (dist < best) { best = dist; bi = khalf + k; }
        }
        sdist[h * 256 + row0] = best; sidx[h * 256 + row0] = bi;
    }
    {
        float lo, hi;
        upk2(z2r1, lo, hi);
        float z2s = lo + hi;
        float best = 3.4e38f; int bi = 0;
        #pragma unroll
        for (int k = 0; k < 8; k++) {
            upk2(acc1[k], lo, hi);
            float dot = lo + hi;
            float dist = (z2s - 2.0f * dot) + c2s[khalf + k];
            if (dist < best) { best = dist; bi = khalf + k; }
        }
        sdist[h * 256 + row1] = best; sidx[h * 256 + row1] = bi;
    }
    __syncthreads();

    // ---- combine halves (half0 wins ties == sequential first-min over k=0..15) ----
    {
        const int r = rowbase + t;
        const bool active = r < nrows;
        float d0 = sdist[t], d1 = sdist[256 + t];
        int   bfin  = (d1 < d0) ? sidx[256 + t] : sidx[t];
        float rloss = (d1 < d0) ? d1 : d0;
        if (!active) rloss = 0.f;
        if (active && idxp) idxp[r] = (float)bfin;
        sidx[t]  = bfin;
        sdist[t] = rloss;
    }
    __syncthreads();

    // ---- cooperative coalesced z_q write: two rows per iteration ----
    float4* zqg = (float4*)zq;
    const int rmax = min(RPB, nrows - rowbase);
    const int rofs = t >> 7;             // 0 or 1
    const int col  = t & 127;
    for (int q = 0; q < RPB; q += 2) {
        int rr = q + rofs;
        if (rr < rmax) {
            int b = sidx[rr];                                   // broadcast
            float4 cv = *(const float4*)(sc + b * DD + col * 4);
            zqg[(size_t)(rowbase + rr) * (DD / 4) + col] = cv;  // coalesced STG.128
        }
    }

    // ---- deterministic block loss partial (tree over 256) ----
    #pragma unroll
    for (int s2 = 128; s2 > 0; s2 >>= 1) {
        if (t < s2) sdist[t] += sdist[t + s2];
        __syncthreads();
    }
    if (t == 0) g_bsum[blockIdx.x] = sdist[0];

    // ---- last-block finalize (deterministic order; counter reset for graph replay) ----
    if (t == 0) {
        __threadfence();
        ticket[0] = atomicAdd(&g_done, 1u);
    }
    __syncthreads();
    if (ticket[0] == (unsigned)(nblocks - 1)) {
        float s = 0.f;
        for (int i = t; i < nblocks; i += TPB) s += __ldcg(&g_bsum[i]);
        sdist[t] = s;
        __syncthreads();
        #pragma unroll
        for (int s2 = 128; s2 > 0; s2 >>= 1) {
            if (t < s2) sdist[t] += sdist[t + s2];
            __syncthreads();
        }
        if (t == 0) {
            if (lossp) lossp[0] = sdist[0] * scale;
            g_done = 0;
        }
    }
    #undef ISSUE
}

extern "C" void kernel_launch(void* const* d_in, const int* in_sizes, int n_in,
                              void* d_out, int out_size) {
    const float* z  = (const float*)d_in[0];
    const float* cb = (const float*)d_in[1];
    int zn = in_sizes[0];          // N * D
    int N  = zn / DD;

    float* zq = (float*)d_out;
    int has_idx  = (out_size >= zn + N) ? 1 : 0;
    float* idxp  = has_idx ? ((float*)d_out + zn) : nullptr;
    float* lossp = (out_size >= zn + N + 1) ? ((float*)d_out + zn + N) : nullptr;

    int nb = (N + RPB - 1) / RPB;
    float scale = 1.25f / ((float)N * (float)DD);

    cudaFuncSetAttribute(vq_fused, cudaFuncAttributeMaxDynamicSharedMemorySize, SM_TOTAL);
    vq_fused<<<nb, TPB, SM_TOTAL>>>(z, cb, zq, idxp, lossp, N, nb, scale);
}

// round 12
// speedup vs baseline: 1.2378x; 1.2378x over previous
#include <cuda_runtime.h>

#define DD   512
#define KK   16
#define TPB  256           // 8 warps; warp owns 32 rows, all 16 k
#define RPB  256           // rows per block
#define CH   32            // dims per chunk = 128B per row = one sector
#define NCH  (DD/CH)       // 16 chunks

// ---- dynamic smem layout (bytes) ---- (no codebook copy anymore)
#define SM_ZSTG   0                       // staging: 2 stages * 8 warps * 4096 = 65536
#define SM_SDIST  65536                   // 256 * 4
#define SM_SIDX   66560                   // 256 * 4
#define SM_C2S    67584                   // 16 * 4
#define SM_TICKET 67648                   // 4
#define SM_TOTAL  67712

// ---- device scratch (no allocations allowed) ----
__device__ float g_bsum[4096];
__device__ unsigned int g_done = 0;

// ---- packed f32x2 helpers (Blackwell FFMA2) ----
__device__ __forceinline__ void upk2(unsigned long long v, float& lo, float& hi) {
    asm("mov.b64 {%0,%1}, %2;" : "=f"(lo), "=f"(hi) : "l"(v));
}
__device__ __forceinline__ unsigned long long ffma2(unsigned long long a,
                                                    unsigned long long b,
                                                    unsigned long long c) {
    unsigned long long d;
    asm("fma.rn.f32x2 %0, %1, %2, %3;" : "=l"(d) : "l"(a), "l"(b), "l"(c));
    return d;
}
__device__ __forceinline__ void cpasync16(unsigned dst, const void* src) {
    asm volatile("cp.async.cg.shared.global [%0], [%1], 16;" :: "r"(dst), "l"(src) : "memory");
}
#define CP_COMMIT() asm volatile("cp.async.commit_group;" ::: "memory")
#define CP_WAIT(n)  asm volatile("cp.async.wait_group %0;" :: "n"(n) : "memory")

__global__ void __launch_bounds__(TPB, 2) vq_fused(
    const float* __restrict__ z, const float* __restrict__ cb,
    float* __restrict__ zq, float* __restrict__ idxp, float* __restrict__ lossp,
    int nrows, int nblocks, float scale)
{
    extern __shared__ char smem[];
    float*        sdist  = (float*)(smem + SM_SDIST);
    int*          sidx   = (int*)(smem + SM_SIDX);
    float*        c2s    = (float*)(smem + SM_C2S);
    unsigned int* ticket = (unsigned int*)(smem + SM_TICKET);

    const int t = threadIdx.x;
    const int w = t >> 5, lane = t & 31;
    const int rowbase = blockIdx.x * RPB;
    const int lastrow = nrows - 1;

    const unsigned smem_sa = (unsigned)__cvta_generic_to_shared(smem);
    // staging base for (stage s, warp w): SM_ZSTG + (s*8 + w)*4096
    const unsigned stg_w = smem_sa + SM_ZSTG + (unsigned)(w * 4096);
    const int swz = lane & 7;                     // this lane's read swizzle

    // cp.async roles: instruction i stages rows i*4 + (lane>>3), piece jj = lane&3... (lane&7)
    const int srow = lane >> 3;                   // 0..3
    const int sjj  = lane & 7;                    // 0..7

    // issue chunk c into stage s: 8 cp.async of 16B, 4 rows each, full 128B segments
    #define ISSUE(c, s) do {                                                        \
        _Pragma("unroll")                                                           \
        for (int i = 0; i < 8; i++) {                                               \
            int rr = i * 4 + srow;                                                  \
            int gr = rowbase + w * 32 + rr; if (gr > lastrow) gr = lastrow;         \
            const char* src = (const char*)z + (size_t)gr * (DD * 4)                \
                              + (size_t)(c) * (CH * 4) + sjj * 16;                  \
            unsigned dst = stg_w + (unsigned)((s) * 32768)                          \
                           + (unsigned)(rr * 128 + ((sjj ^ (rr & 7)) << 4));        \
            cpasync16(dst, src);                                                    \
        }                                                                           \
        CP_COMMIT();                                                                \
    } while (0)

    // ---- prologue: stage chunk 0 ----
    ISSUE(0, 0);

    // ---- codebook squared norms from GLOBAL (identical per-k arithmetic) ----
    // also warms L1 with the whole 32 KB codebook
    #pragma unroll
    for (int kk = 0; kk < 2; kk++) {
        int k = w * 2 + kk;
        float s = 0.f;
        for (int j = lane; j < DD; j += 32) {
            float v = cb[k * DD + j];
            s = fmaf(v, v, s);
        }
        #pragma unroll
        for (int o = 16; o; o >>= 1) s += __shfl_xor_sync(0xffffffffu, s, o);
        if (lane == 0) c2s[k] = s;
    }
    __syncthreads();                      // c2s visible; no block syncs until epilogue

    // ---- accumulators: one chain per k, bit-identical order to R9 ----
    unsigned long long acc[KK];
    #pragma unroll
    for (int k = 0; k < KK; k++) acc[k] = 0ull;
    unsigned long long z2 = 0ull;

    const char* stg_rd = (const char*)smem + SM_ZSTG + w * 4096 + lane * 128;

    for (int c = 0; c < NCH; c++) {
        if (c + 1 < NCH) {
            ISSUE(c + 1, (c + 1) & 1);    // overlaps chunk c wait + compute
            CP_WAIT(1);                   // chunk c complete, c+1 in flight
        } else {
            CP_WAIT(0);
        }
        __syncwarp();                     // cross-lane staging visibility (warp-local)

        const char* rb = stg_rd + (c & 1) * 32768;
        const float* cbb = cb + c * CH;   // GLOBAL codebook, L1-resident

        #pragma unroll
        for (int jg = 0; jg < 8; jg++) {  // 8 x 4-dim groups
            ulonglong2 zv = *(const ulonglong2*)(rb + ((jg ^ swz) << 4));
            z2 = ffma2(zv.x, zv.x, z2);
            z2 = ffma2(zv.y, zv.y, z2);
            #pragma unroll
            for (int k = 0; k < KK; k++) {
                // broadcast LDG.128 (same address across lanes) -> 1 L1 wavefront
                ulonglong2 cv = *(const ulonglong2*)(cbb + k * DD + jg * 4);
                acc[k] = ffma2(zv.x, cv.x, acc[k]);
                acc[k] = ffma2(zv.y, cv.y, acc[k]);
            }
        }
        __syncwarp();                     // all lanes done reading before next overwrite
    }

    // ---- argmin with reference-matching quantization (seq k=0..15, strict <) ----
    {
        float lo, hi;
        upk2(z2, lo, hi);
        float z2s = lo + hi;
        float best = 3.4e38f; int bi = 0;
        #pragma unroll
        for (int k = 0; k < KK; k++) {
            upk2(acc[k], lo, hi);
            float dot = lo + hi;
            float dist = (z2s - 2.0f * dot) + c2s[k];
            if (dist < best) { best = dist; bi = k; }
        }
        const int r = rowbase + t;        // thread t's row == block-local t
        const bool active = r < nrows;
        sdist[t] = active ? best : 0.f;
        sidx[t]  = bi;
        if (active && idxp) idxp[r] = (float)bi;
    }
    __syncthreads();

    // ---- cooperative coalesced z_q write: two rows per iteration ----
    float4* zqg = (float4*)zq;
    const int rmax = min(RPB, nrows - rowbase);
    const int rofs = t >> 7;              // 0 or 1
    const int col  = t & 127;
    for (int p = 0; p < RPB; p += 2) {
        int rr = p + rofs;
        if (rr < rmax) {
            int b = sidx[rr];                                   // broadcast
            float4 cv = *(const float4*)(cb + b * DD + col * 4);// L1-hit coalesced LDG
            zqg[(size_t)(rowbase + rr) * (DD / 4) + col] = cv;  // coalesced STG.128
        }
    }

    // ---- deterministic block loss partial (tree over 256) ----
    #pragma unroll
    for (int s2 = 128; s2 > 0; s2 >>= 1) {
        if (t < s2) sdist[t] += sdist[t + s2];
        __syncthreads();
    }
    if (t == 0) g_bsum[blockIdx.x] = sdist[0];

    // ---- last-block finalize (deterministic order; counter reset for graph replay) ----
    if (t == 0) {
        __threadfence();
        ticket[0] = atomicAdd(&g_done, 1u);
    }
    __syncthreads();
    if (ticket[0] == (unsigned)(nblocks - 1)) {
        float s = 0.f;
        for (int i = t; i < nblocks; i += TPB) s += __ldcg(&g_bsum[i]);
        sdist[t] = s;
        __syncthreads();
        #pragma unroll
        for (int s2 = 128; s2 > 0; s2 >>= 1) {
            if (t < s2) sdist[t] += sdist[t + s2];
            __syncthreads();
        }
        if (t == 0) {
            if (lossp) lossp[0] = sdist[0] * scale;
            g_done = 0;
        }
    }
    #undef ISSUE
}

extern "C" void kernel_launch(void* const* d_in, const int* in_sizes, int n_in,
                              void* d_out, int out_size) {
    const float* z  = (const float*)d_in[0];
    const float* cb = (const float*)d_in[1];
    int zn = in_sizes[0];          // N * D
    int N  = zn / DD;

    float* zq = (float*)d_out;
    int has_idx  = (out_size >= zn + N) ? 1 : 0;
    float* idxp  = has_idx ? ((float*)d_out + zn) : nullptr;
    float* lossp = (out_size >= zn + N + 1) ? ((float*)d_out + zn + N) : nullptr;

    int nb = (N + RPB - 1) / RPB;
    float scale = 1.25f / ((float)N * (float)DD);

    cudaFuncSetAttribute(vq_fused, cudaFuncAttributeMaxDynamicSharedMemorySize, SM_TOTAL);
    vq_fused<<<nb, TPB, SM_TOTAL>>>(z, cb, zq, idxp, lossp, N, nb, scale);
}

// round 14
// speedup vs baseline: 2.0422x; 1.6499x over previous
#include <cuda_runtime.h>

#define DD   512
#define KK   16
#define TPB  256           // 8 warps; warp owns 64 rows (2/thread), all 16 k
#define RPB  512           // rows per block
#define CH   32            // dims per chunk = 128B per row = one sector
#define NCH  (DD/CH)       // 16 chunks

// ---- dynamic smem layout (bytes) ----
#define SM_CB     0                       // codebook: 32768
#define SM_ZSTG   32768                   // staging: 2 stages * 8 warps * 8192 = 131072
#define SM_SIDX   163840                  // 512 * 4 = 2048
#define SM_SDIST  165888                  // 256 * 4 = 1024
#define SM_C2S    166912                  // 16 * 4
#define SM_TICKET 166976                  // 4
#define SM_TOTAL  167040

// ---- device scratch (no allocations allowed) ----
__device__ float g_bsum[4096];
__device__ unsigned int g_done = 0;

// ---- packed f32x2 helpers (Blackwell FFMA2) ----
__device__ __forceinline__ void upk2(unsigned long long v, float& lo, float& hi) {
    asm("mov.b64 {%0,%1}, %2;" : "=f"(lo), "=f"(hi) : "l"(v));
}
__device__ __forceinline__ unsigned long long ffma2(unsigned long long a,
                                                    unsigned long long b,
                                                    unsigned long long c) {
    unsigned long long d;
    asm("fma.rn.f32x2 %0, %1, %2, %3;" : "=l"(d) : "l"(a), "l"(b), "l"(c));
    return d;
}
__device__ __forceinline__ void cpasync16(unsigned dst, const void* src) {
    asm volatile("cp.async.cg.shared.global [%0], [%1], 16;" :: "r"(dst), "l"(src) : "memory");
}
#define CP_COMMIT() asm volatile("cp.async.commit_group;" ::: "memory")
#define CP_WAIT(n)  asm volatile("cp.async.wait_group %0;" :: "n"(n) : "memory")

__global__ void __launch_bounds__(TPB, 1) vq_fused(
    const float* __restrict__ z, const float* __restrict__ cb,
    float* __restrict__ zq, float* __restrict__ idxp, float* __restrict__ lossp,
    int nrows, int nblocks, float scale)
{
    extern __shared__ char smem[];
    float*        sc     = (float*)(smem + SM_CB);
    int*          sidx   = (int*)(smem + SM_SIDX);      // [512]
    float*        sdist  = (float*)(smem + SM_SDIST);   // [256] per-thread loss
    float*        c2s    = (float*)(smem + SM_C2S);
    unsigned int* ticket = (unsigned int*)(smem + SM_TICKET);

    const int t = threadIdx.x;
    const int w = t >> 5, lane = t & 31;
    const int rowbase = blockIdx.x * RPB;
    const int lastrow = nrows - 1;

    const unsigned smem_sa = (unsigned)__cvta_generic_to_shared(smem);
    // staging for (stage s, warp w): SM_ZSTG + (s*8 + w)*8192
    // inside: row_local*128 + ((piece ^ (row_local&7))<<4)   (R9 swizzle)
    const unsigned stg_w = smem_sa + SM_ZSTG + (unsigned)(w * 8192);
    const int swz = lane & 7;                     // read swizzle (same for lane and lane+32)

    // cp.async roles: instr i stages row i*4 + (lane>>3), piece = lane&7
    const int srow = lane >> 3;                   // 0..3
    const int sjj  = lane & 7;                    // 0..7

    // issue chunk c into stage s: 16 cp.async of 16B, full 128B segments per row
    #define ISSUE(c, s) do {                                                        \
        _Pragma("unroll")                                                           \
        for (int i = 0; i < 16; i++) {                                              \
            int rr = i * 4 + srow;                                                  \
            int gr = rowbase + w * 64 + rr; if (gr > lastrow) gr = lastrow;         \
            const char* src = (const char*)z + (size_t)gr * (DD * 4)                \
                              + (size_t)(c) * (CH * 4) + sjj * 16;                  \
            unsigned dst = stg_w + (unsigned)((s) * 65536)                          \
                           + (unsigned)(rr * 128 + ((sjj ^ (rr & 7)) << 4));        \
            cpasync16(dst, src);                                                    \
        }                                                                           \
        CP_COMMIT();                                                                \
    } while (0)

    // ---- prologue: stage chunk 0 ----
    ISSUE(0, 0);

    // ---- stage codebook (coalesced float4) ----
    for (int i = t; i < KK * DD / 4; i += TPB)
        ((float4*)sc)[i] = ((const float4*)cb)[i];
    __syncthreads();

    // ---- codebook squared norms (identical per-k arithmetic as before) ----
    #pragma unroll
    for (int kk = 0; kk < 2; kk++) {
        int k = w * 2 + kk;
        float s = 0.f;
        for (int j = lane; j < DD; j += 32) {
            float v = sc[k * DD + j];
            s = fmaf(v, v, s);
        }
        #pragma unroll
        for (int o = 16; o; o >>= 1) s += __shfl_xor_sync(0xffffffffu, s, o);
        if (lane == 0) c2s[k] = s;
    }
    __syncthreads();                      // c2s + sc visible; no block syncs until epilogue

    // ---- accumulators: 16 k x 2 rows, single chain each (R10's exact structure) ----
    unsigned long long acc0[KK], acc1[KK];
    #pragma unroll
    for (int k = 0; k < KK; k++) { acc0[k] = 0ull; acc1[k] = 0ull; }
    unsigned long long z2r0 = 0ull, z2r1 = 0ull;

    const char* stg_rd = (const char*)smem + SM_ZSTG + w * 8192;

    for (int c = 0; c < NCH; c++) {
        if (c + 1 < NCH) {
            ISSUE(c + 1, (c + 1) & 1);    // overlaps chunk c wait + compute
            CP_WAIT(1);                   // chunk c complete, c+1 in flight
        } else {
            CP_WAIT(0);
        }
        __syncwarp();                     // cross-lane staging visibility (warp-local)

        const char* rb0 = stg_rd + (c & 1) * 65536 + lane * 128;
        const char* rb1 = rb0 + 32 * 128;
        const float* cbb = sc + c * CH;

        #pragma unroll
        for (int jg = 0; jg < 8; jg++) {  // 8 x 4-dim groups, ascending
            ulonglong2 zv0 = *(const ulonglong2*)(rb0 + ((jg ^ swz) << 4));
            ulonglong2 zv1 = *(const ulonglong2*)(rb1 + ((jg ^ swz) << 4));
            z2r0 = ffma2(zv0.x, zv0.x, z2r0);  z2r0 = ffma2(zv0.y, zv0.y, z2r0);
            z2r1 = ffma2(zv1.x, zv1.x, z2r1);  z2r1 = ffma2(zv1.y, zv1.y, z2r1);
            #pragma unroll
            for (int k = 0; k < KK; k++) {
                // broadcast LDS.128 (same address across lanes), feeds BOTH rows
                ulonglong2 cv = *(const ulonglong2*)(cbb + k * DD + jg * 4);
                acc0[k] = ffma2(zv0.x, cv.x, acc0[k]);
                acc0[k] = ffma2(zv0.y, cv.y, acc0[k]);
                acc1[k] = ffma2(zv1.x, cv.x, acc1[k]);
                acc1[k] = ffma2(zv1.y, cv.y, acc1[k]);
            }
        }
        __syncwarp();                     // all lanes done reading before next overwrite
    }

    // ---- argmin with reference-matching quantization (seq k=0..15, strict <) ----
    const int row0 = w * 64 + lane;       // block-local
    const int row1 = row0 + 32;
    float rloss = 0.f;
    {
        float lo, hi;
        upk2(z2r0, lo, hi);
        float z2s = lo + hi;
        float best = 3.4e38f; int bi = 0;
        #pragma unroll
        for (int k = 0; k < KK; k++) {
            upk2(acc0[k], lo, hi);
            float dot = lo + hi;
            float dist = (z2s - 2.0f * dot) + c2s[k];
            if (dist < best) { best = dist; bi = k; }
        }
        const int r = rowbase + row0;
        const bool active = r < nrows;
        if (active) rloss += best;
        sidx[row0] = bi;
        if (active && idxp) idxp[r] = (float)bi;
    }
    {
        float lo, hi;
        upk2(z2r1, lo, hi);
        float z2s = lo + hi;
        float best = 3.4e38f; int bi = 0;
        #pragma unroll
        for (int k = 0; k < KK; k++) {
            upk2(acc1[k], lo, hi);
            float dot = lo + hi;
            float dist = (z2s - 2.0f * dot) + c2s[k];
            if (dist < best) { best = dist; bi = k; }
        }
        const int r = rowbase + row1;
        const bool active = r < nrows;
        if (active) rloss += best;
        sidx[row1] = bi;
        if (active && idxp) idxp[r] = (float)bi;
    }
    sdist[t] = rloss;
    __syncthreads();

    // ---- cooperative coalesced z_q write: two rows per iteration ----
    float4* zqg = (float4*)zq;
    const int rmax = min(RPB, nrows - rowbase);
    const int rofs = t >> 7;              // 0 or 1
    const int col  = t & 127;
    for (int p = 0; p < RPB; p += 2) {
        int rr = p + rofs;
        if (rr < rmax) {
            int b = sidx[rr];                                   // broadcast
            float4 cv = *(const float4*)(sc + b * DD + col * 4);
            zqg[(size_t)(rowbase + rr) * (DD / 4) + col] = cv;  // coalesced STG.128
        }
    }

    // ---- deterministic block loss partial (tree over 256) ----
    #pragma unroll
    for (int s2 = 128; s2 > 0; s2 >>= 1) {
        if (t < s2) sdist[t] += sdist[t + s2];
        __syncthreads();
    }
    if (t == 0) g_bsum[blockIdx.x] = sdist[0];

    // ---- last-block finalize (deterministic order; counter reset for graph replay) ----
    if (t == 0) {
        __threadfence();
        ticket[0] = atomicAdd(&g_done, 1u);
    }
    __syncthreads();
    if (ticket[0] == (unsigned)(nblocks - 1)) {
        float s = 0.f;
        for (int i = t; i < nblocks; i += TPB) s += __ldcg(&g_bsum[i]);
        sdist[t] = s;
        __syncthreads();
        #pragma unroll
        for (int s2 = 128; s2 > 0; s2 >>= 1) {
            if (t < s2) sdist[t] += sdist[t + s2];
            __syncthreads();
        }
        if (t == 0) {
            if (lossp) lossp[0] = sdist[0] * scale;
            g_done = 0;
        }
    }
    #undef ISSUE
}

extern "C" void kernel_launch(void* const* d_in, const int* in_sizes, int n_in,
                              void* d_out, int out_size) {
    const float* z  = (const float*)d_in[0];
    const float* cb = (const float*)d_in[1];
    int zn = in_sizes[0];          // N * D
    int N  = zn / DD;

    float* zq = (float*)d_out;
    int has_idx  = (out_size >= zn + N) ? 1 : 0;
    float* idxp  = has_idx ? ((float*)d_out + zn) : nullptr;
    float* lossp = (out_size >= zn + N + 1) ? ((float*)d_out + zn + N) : nullptr;

    int nb = (N + RPB - 1) / RPB;
    float scale = 1.25f / ((float)N * (float)DD);

    cudaFuncSetAttribute(vq_fused, cudaFuncAttributeMaxDynamicSharedMemorySize, SM_TOTAL);
    vq_fused<<<nb, TPB, SM_TOTAL>>>(z, cb, zq, idxp, lossp, N, nb, scale);
}